// round 1
// baseline (speedup 1.0000x reference)
#include <cuda_runtime.h>
#include <math.h>

#define DIM   2048
#define SEQ   2048
#define NH    32
#define KVH   8
#define HD    64
#define NE    8
#define FF    7168
#define CAP   2048

// ---------------- scratch (device globals; no allocation allowed) -------------
static __device__ float g_hn  [SEQ * DIM];           // rmsnorm1 out, reused for O-proj out
static __device__ float g_q   [SEQ * NH * HD];
static __device__ float g_k   [SEQ * KVH * HD];
static __device__ float g_v   [SEQ * KVH * HD];
static __device__ float g_attn[SEQ * NH * HD];
static __device__ float g_h2  [SEQ * DIM];           // residual after attention
static __device__ float g_hn2 [SEQ * DIM];           // rmsnorm2 out
static __device__ float g_gate[(size_t)NE * CAP * FF];   // gate, then act (silu*up)
static __device__ float g_up  [(size_t)NE * CAP * FF];
static __device__ float g_down[(size_t)NE * CAP * DIM];
static __device__ int   g_cnt [NE];
static __device__ int   g_list[NE * CAP];
static __device__ int   g_eid [SEQ * 2];
static __device__ int   g_slot[SEQ * 2];
static __device__ float g_w   [SEQ * 2];

// ---------------- small kernels ----------------------------------------------
__global__ void zero_cnt_kernel() {
    if (threadIdx.x < NE) g_cnt[threadIdx.x] = 0;
}

__global__ void rmsnorm_kernel(const float* __restrict__ x,
                               const float* __restrict__ w,
                               float* __restrict__ o) {
    int row = blockIdx.x;
    const float* xr = x + (size_t)row * DIM;
    float s = 0.f;
    for (int i = threadIdx.x; i < DIM; i += blockDim.x) {
        float v = xr[i];
        s += v * v;
    }
    __shared__ float red[32];
    int lane = threadIdx.x & 31, wid = threadIdx.x >> 5;
    #pragma unroll
    for (int off = 16; off; off >>= 1) s += __shfl_down_sync(0xffffffffu, s, off);
    if (lane == 0) red[wid] = s;
    __syncthreads();
    if (wid == 0) {
        float t = (lane < (blockDim.x >> 5)) ? red[lane] : 0.f;
        #pragma unroll
        for (int off = 16; off; off >>= 1) t += __shfl_down_sync(0xffffffffu, t, off);
        if (lane == 0) red[0] = t;
    }
    __syncthreads();
    float scale = rsqrtf(red[0] / (float)DIM + 1e-5f);
    float* orow = o + (size_t)row * DIM;
    for (int i = threadIdx.x; i < DIM; i += blockDim.x)
        orow[i] = xr[i] * scale * w[i];
}

__global__ void add_kernel(const float* __restrict__ a,
                           const float* __restrict__ b,
                           float* __restrict__ o, int n) {
    int i = blockIdx.x * blockDim.x + threadIdx.x;
    if (i < n) o[i] = a[i] + b[i];
}

// RoPE in-place on [SEQ][heads*HD]
__global__ void rope_kernel(float* __restrict__ x, const int* __restrict__ pos, int heads) {
    int idx = blockIdx.x * blockDim.x + threadIdx.x;
    int total = SEQ * heads * (HD / 2);
    if (idx >= total) return;
    int d = idx & 31;
    int t = idx >> 5;
    int h = t % heads;
    int s = t / heads;
    double invd = pow(1.0e6, -(double)d / 32.0);
    float ang = (float)((double)pos[s] * invd);
    float c, sn;
    sincosf(ang, &sn, &c);
    float* p = x + ((size_t)s * heads + h) * HD;
    float x1 = p[d], x2 = p[d + 32];
    p[d]      = x1 * c - x2 * sn;
    p[d + 32] = x2 * c + x1 * sn;
}

// ---------------- attention (flash style, 64 queries / block) -----------------
__global__ void __launch_bounds__(64)
attn_kernel(const float* __restrict__ q, const float* __restrict__ k,
            const float* __restrict__ v, float* __restrict__ o) {
    __shared__ float Ks[64][64];
    __shared__ float Vs[64][64];
    __shared__ float Ss[64][65];
    int qt = blockIdx.x, h = blockIdx.y;
    int tid = threadIdx.x;
    int row = qt * 64 + tid;
    int kvh = h >> 2;   // GQA repeat = 4

    float qr[64], acc[64];
    const float* qp = q + (size_t)row * (NH * HD) + h * HD;
    #pragma unroll
    for (int i = 0; i < 16; i++) ((float4*)qr)[i] = ((const float4*)qp)[i];
    #pragma unroll
    for (int i = 0; i < 64; i++) acc[i] = 0.f;
    float m = -1e30f, l = 0.f;

    for (int kt = 0; kt <= qt; kt++) {
        const float* kp = k + (size_t)(kt * 64 + tid) * (KVH * HD) + kvh * HD;
        const float* vp = v + (size_t)(kt * 64 + tid) * (KVH * HD) + kvh * HD;
        #pragma unroll
        for (int i = 0; i < 16; i++) {
            ((float4*)Ks[tid])[i] = ((const float4*)kp)[i];
            ((float4*)Vs[tid])[i] = ((const float4*)vp)[i];
        }
        __syncthreads();

        int jmax = (kt == qt) ? (tid + 1) : 64;
        float mloc = -1e30f;
        for (int j = 0; j < jmax; j++) {
            float s = 0.f;
            #pragma unroll
            for (int d = 0; d < 64; d += 4) {
                float4 k4 = *(const float4*)&Ks[j][d];
                s += qr[d] * k4.x + qr[d + 1] * k4.y + qr[d + 2] * k4.z + qr[d + 3] * k4.w;
            }
            s *= 0.125f;
            Ss[tid][j] = s;
            mloc = fmaxf(mloc, s);
        }
        float mnew = fmaxf(m, mloc);
        float sc = expf(m - mnew);
        l *= sc;
        #pragma unroll
        for (int d = 0; d < 64; d++) acc[d] *= sc;
        for (int j = 0; j < jmax; j++) {
            float p = expf(Ss[tid][j] - mnew);
            l += p;
            #pragma unroll
            for (int d = 0; d < 64; d += 4) {
                float4 v4 = *(const float4*)&Vs[j][d];
                acc[d]     += p * v4.x;
                acc[d + 1] += p * v4.y;
                acc[d + 2] += p * v4.z;
                acc[d + 3] += p * v4.w;
            }
        }
        m = mnew;
        __syncthreads();
    }
    float inv = 1.f / l;
    float* op = o + (size_t)row * (NH * HD) + h * HD;
    #pragma unroll
    for (int d = 0; d < 64; d++) op[d] = acc[d] * inv;
}

// ---------------- generic 128x128x8 SGEMM, optional gather + device-M ---------
__global__ void __launch_bounds__(256, 2)
gemm_kernel(const float* __restrict__ A, const float* __restrict__ B,
            float* __restrict__ C, int M, int N, int K,
            const int* __restrict__ rowmap, const int* __restrict__ cnt,
            size_t strideA, size_t strideB, size_t strideC) {
    int e = blockIdx.z;
    int m = cnt ? cnt[e] : M;
    if ((int)blockIdx.y * 128 >= m) return;

    const float* Ab = A + strideA * (size_t)e;
    const float* Bb = B + strideB * (size_t)e;
    float*       Cb = C + strideC * (size_t)e;
    const int*   rm = rowmap ? rowmap + e * CAP : (const int*)0;

    __shared__ float As[8][128];
    __shared__ float Bs[8][128];

    int tid = threadIdx.x;
    int tx = tid & 15, ty = tid >> 4;

    int aRow = tid >> 1;
    int aCol = (tid & 1) * 4;
    int bRow = tid >> 5;
    int bCol = (tid & 31) * 4;

    int gARow = blockIdx.y * 128 + aRow;
    bool aValid = (gARow < m);
    int srcRow = aValid ? (rm ? rm[gARow] : gARow) : 0;
    const float* Ap = Ab + (size_t)srcRow * K + aCol;
    const float* Bp = Bb + (size_t)bRow * N + (size_t)blockIdx.x * 128 + bCol;

    float acc[8][8];
    #pragma unroll
    for (int i = 0; i < 8; i++)
        #pragma unroll
        for (int j = 0; j < 8; j++) acc[i][j] = 0.f;

    for (int k0 = 0; k0 < K; k0 += 8) {
        float4 av = make_float4(0.f, 0.f, 0.f, 0.f);
        if (aValid) av = *(const float4*)(Ap + k0);
        As[aCol + 0][aRow] = av.x;
        As[aCol + 1][aRow] = av.y;
        As[aCol + 2][aRow] = av.z;
        As[aCol + 3][aRow] = av.w;
        *(float4*)&Bs[bRow][bCol] = *(const float4*)(Bp + (size_t)k0 * N);
        __syncthreads();

        #pragma unroll
        for (int kk = 0; kk < 8; kk++) {
            float ar[8], br[8];
            *(float4*)(ar)     = *(float4*)&As[kk][ty * 8];
            *(float4*)(ar + 4) = *(float4*)&As[kk][ty * 8 + 4];
            *(float4*)(br)     = *(float4*)&Bs[kk][tx * 8];
            *(float4*)(br + 4) = *(float4*)&Bs[kk][tx * 8 + 4];
            #pragma unroll
            for (int i = 0; i < 8; i++)
                #pragma unroll
                for (int j = 0; j < 8; j++) acc[i][j] += ar[i] * br[j];
        }
        __syncthreads();
    }

    #pragma unroll
    for (int i = 0; i < 8; i++) {
        int r = blockIdx.y * 128 + ty * 8 + i;
        if (r < m) {
            float* cp = Cb + (size_t)r * N + (size_t)blockIdx.x * 128 + tx * 8;
            *(float4*)cp       = make_float4(acc[i][0], acc[i][1], acc[i][2], acc[i][3]);
            *(float4*)(cp + 4) = make_float4(acc[i][4], acc[i][5], acc[i][6], acc[i][7]);
        }
    }
}

// ---------------- router: logits, top-2 (softmax-Z cancels), token lists ------
__global__ void router_kernel(const float* __restrict__ x, const float* __restrict__ Wr) {
    int warp = (blockIdx.x * blockDim.x + threadIdx.x) >> 5;
    int lane = threadIdx.x & 31;
    if (warp >= SEQ) return;
    const float* xr = x + (size_t)warp * DIM;
    float acc[NE];
    #pragma unroll
    for (int e = 0; e < NE; e++) acc[e] = 0.f;
    for (int d = lane; d < DIM; d += 32) {
        float xv = xr[d];
        #pragma unroll
        for (int e = 0; e < NE; e++) acc[e] += xv * Wr[d * NE + e];
    }
    #pragma unroll
    for (int e = 0; e < NE; e++)
        #pragma unroll
        for (int off = 16; off; off >>= 1)
            acc[e] += __shfl_down_sync(0xffffffffu, acc[e], off);
    if (lane == 0) {
        int i1 = 0;
        #pragma unroll
        for (int e = 1; e < NE; e++) if (acc[e] > acc[i1]) i1 = e;
        int i2 = (i1 == 0) ? 1 : 0;
        #pragma unroll
        for (int e = 0; e < NE; e++) if (e != i1 && acc[e] > acc[i2]) i2 = e;
        float w1 = 1.f / (1.f + expf(acc[i2] - acc[i1]));   // renormalized top-2 weight
        int s0 = atomicAdd(&g_cnt[i1], 1);
        int s1 = atomicAdd(&g_cnt[i2], 1);
        g_list[i1 * CAP + s0] = warp;
        g_list[i2 * CAP + s1] = warp;
        g_eid[warp * 2]  = i1; g_eid[warp * 2 + 1]  = i2;
        g_slot[warp * 2] = s0; g_slot[warp * 2 + 1] = s1;
        g_w[warp * 2]    = w1; g_w[warp * 2 + 1]    = 1.f - w1;
    }
}

__global__ void silu_mul_kernel() {
    int e = blockIdx.z;
    int r = blockIdx.y;
    if (r >= g_cnt[e]) return;
    size_t base = ((size_t)e * CAP + r) * FF;
    int c = blockIdx.x * blockDim.x + threadIdx.x;
    float g = g_gate[base + c];
    float u = g_up[base + c];
    g_gate[base + c] = (g / (1.f + expf(-g))) * u;
}

__global__ void combine_kernel(float* __restrict__ out) {
    int idx = blockIdx.x * blockDim.x + threadIdx.x;
    if (idx >= SEQ * DIM) return;
    int n = idx >> 11;
    int d = idx & (DIM - 1);
    int e0 = g_eid[n * 2],  e1 = g_eid[n * 2 + 1];
    int s0 = g_slot[n * 2], s1 = g_slot[n * 2 + 1];
    out[idx] = g_h2[idx]
             + g_w[n * 2]     * g_down[((size_t)e0 * CAP + s0) * DIM + d]
             + g_w[n * 2 + 1] * g_down[((size_t)e1 * CAP + s1) * DIM + d];
}

// ---------------- launch ------------------------------------------------------
extern "C" void kernel_launch(void* const* d_in, const int* in_sizes, int n_in,
                              void* d_out, int out_size) {
    const float* hidden = (const float*)d_in[0];
    const int*   pos    = (const int*)  d_in[1];
    const float* ln1    = (const float*)d_in[2];
    const float* Wq     = (const float*)d_in[3];
    const float* Wk     = (const float*)d_in[4];
    const float* Wv     = (const float*)d_in[5];
    const float* Wo     = (const float*)d_in[6];
    const float* ln2    = (const float*)d_in[7];
    const float* Wr     = (const float*)d_in[8];
    const float* W1     = (const float*)d_in[9];
    const float* W3     = (const float*)d_in[10];
    const float* W2     = (const float*)d_in[11];
    float* out = (float*)d_out;

    float *p_hn, *p_q, *p_k, *p_v, *p_attn, *p_h2, *p_hn2, *p_gate, *p_up, *p_down;
    cudaGetSymbolAddress((void**)&p_hn,   g_hn);
    cudaGetSymbolAddress((void**)&p_q,    g_q);
    cudaGetSymbolAddress((void**)&p_k,    g_k);
    cudaGetSymbolAddress((void**)&p_v,    g_v);
    cudaGetSymbolAddress((void**)&p_attn, g_attn);
    cudaGetSymbolAddress((void**)&p_h2,   g_h2);
    cudaGetSymbolAddress((void**)&p_hn2,  g_hn2);
    cudaGetSymbolAddress((void**)&p_gate, g_gate);
    cudaGetSymbolAddress((void**)&p_up,   g_up);
    cudaGetSymbolAddress((void**)&p_down, g_down);
    int* p_cnt;  cudaGetSymbolAddress((void**)&p_cnt,  g_cnt);
    int* p_list; cudaGetSymbolAddress((void**)&p_list, g_list);

    zero_cnt_kernel<<<1, 32>>>();

    // pre-attention norm + QKV
    rmsnorm_kernel<<<SEQ, 256>>>(hidden, ln1, p_hn);
    gemm_kernel<<<dim3(DIM / 128, SEQ / 128, 1), 256>>>(p_hn, Wq, p_q, SEQ, NH * HD, DIM, 0, 0, 0, 0, 0);
    gemm_kernel<<<dim3((KVH * HD) / 128, SEQ / 128, 1), 256>>>(p_hn, Wk, p_k, SEQ, KVH * HD, DIM, 0, 0, 0, 0, 0);
    gemm_kernel<<<dim3((KVH * HD) / 128, SEQ / 128, 1), 256>>>(p_hn, Wv, p_v, SEQ, KVH * HD, DIM, 0, 0, 0, 0, 0);

    rope_kernel<<<(SEQ * NH * (HD / 2) + 255) / 256, 256>>>(p_q, pos, NH);
    rope_kernel<<<(SEQ * KVH * (HD / 2) + 255) / 256, 256>>>(p_k, pos, KVH);

    attn_kernel<<<dim3(SEQ / 64, NH, 1), 64>>>(p_q, p_k, p_v, p_attn);

    // O projection + residual
    gemm_kernel<<<dim3(DIM / 128, SEQ / 128, 1), 256>>>(p_attn, Wo, p_hn, SEQ, DIM, NH * HD, 0, 0, 0, 0, 0);
    add_kernel<<<(SEQ * DIM + 255) / 256, 256>>>(hidden, p_hn, p_h2, SEQ * DIM);

    // post-attention norm + router
    rmsnorm_kernel<<<SEQ, 256>>>(p_h2, ln2, p_hn2);
    router_kernel<<<(SEQ * 32 + 255) / 256, 256>>>(p_hn2, Wr);

    // routed expert GEMMs (gridDim.z = expert, early-exit by device count)
    gemm_kernel<<<dim3(FF / 128, CAP / 128, NE), 256>>>(
        p_hn2, W1, p_gate, CAP, FF, DIM, p_list, p_cnt,
        0, (size_t)DIM * FF, (size_t)CAP * FF);
    gemm_kernel<<<dim3(FF / 128, CAP / 128, NE), 256>>>(
        p_hn2, W3, p_up, CAP, FF, DIM, p_list, p_cnt,
        0, (size_t)DIM * FF, (size_t)CAP * FF);
    silu_mul_kernel<<<dim3(FF / 256, CAP, NE), 256>>>();
    gemm_kernel<<<dim3(DIM / 128, CAP / 128, NE), 256>>>(
        p_gate, W2, p_down, CAP, DIM, FF, 0, p_cnt,
        (size_t)CAP * FF, (size_t)FF * DIM, (size_t)CAP * DIM);

    combine_kernel<<<(SEQ * DIM + 255) / 256, 256>>>(out);
}

// round 4
// speedup vs baseline: 1.8698x; 1.8698x over previous
#include <cuda_runtime.h>
#include <cuda_bf16.h>
#include <math.h>
#include <stdint.h>

#define DIM   2048
#define SEQ   2048
#define NH    32
#define KVH   8
#define HD    64
#define NE    8
#define FF    7168
#define CAP   2048
#define QKVN  3072

// ---------------- scratch (device globals) ------------------------------------
static __device__ float g_hn  [SEQ * DIM];
static __device__ float g_wqkv[DIM * QKVN];
static __device__ float g_qkv [SEQ * QKVN];
static __device__ float g_attn[SEQ * NH * HD];
static __device__ float g_h2  [SEQ * DIM];
static __device__ float g_hn2 [SEQ * DIM];
static __device__ float g_xe  [(size_t)NE * CAP * DIM];
static __device__ float g_gate[(size_t)NE * CAP * FF];
static __device__ float g_up  [(size_t)NE * CAP * FF];
static __device__ float g_down[(size_t)NE * CAP * DIM];
static __device__ int   g_cnt [NE];
static __device__ int   g_eid [SEQ * 2];
static __device__ int   g_slot[SEQ * 2];
static __device__ float g_w   [SEQ * 2];

// ---------------- helpers ------------------------------------------------------
// pack (x0 -> low half, x1 -> high half) as bf16x2
__device__ __forceinline__ uint32_t pack2(float x0, float x1) {
    uint32_t u;
    asm("cvt.rn.bf16x2.f32 %0, %1, %2;" : "=r"(u) : "f"(x1), "f"(x0));
    return u;
}
__device__ __forceinline__ void unpack2(uint32_t u, float& f0, float& f1) {
    __nv_bfloat162 t = *reinterpret_cast<__nv_bfloat162*>(&u);
    f0 = __bfloat162float(t.x);
    f1 = __bfloat162float(t.y);
}
__device__ __forceinline__ void mma_bf16(float* d, const uint32_t* a, const uint32_t* b) {
    asm volatile(
        "mma.sync.aligned.m16n8k16.row.col.f32.bf16.bf16.f32 "
        "{%0,%1,%2,%3}, {%4,%5,%6,%7}, {%8,%9}, {%0,%1,%2,%3};"
        : "+f"(d[0]), "+f"(d[1]), "+f"(d[2]), "+f"(d[3])
        : "r"(a[0]), "r"(a[1]), "r"(a[2]), "r"(a[3]), "r"(b[0]), "r"(b[1]));
}

// ---------------- 3xBF16 split-precision GEMM (128x128x32 tile) ----------------
#define BM 128
#define BN 128
#define BK 32
#define A_STRIDE 20                  // u32 per row (16 kpairs + 4 pad)
#define B_STRIDE 136                 // u32 per kpair row (128 n + 8 pad)
#define A_TILE_U32 (BM * A_STRIDE)   // 2560
#define B_TILE_U32 (16 * B_STRIDE)   // 2176
#define BUF_U32 (2 * A_TILE_U32 + 2 * B_TILE_U32)   // 9472
#define GSMEM_BYTES (BUF_U32 * 4)    // 37888

__global__ void __launch_bounds__(256, 1)
gemm_tc(const float* __restrict__ A, const float* __restrict__ B, float* __restrict__ C,
        int M, int N, int K, const int* __restrict__ cnt,
        size_t sA, size_t sB, size_t sC) {
    int e = blockIdx.z;
    int m = cnt ? cnt[e] : M;
    int m0 = blockIdx.y * BM;
    if (m0 >= m) return;
    int n0 = blockIdx.x * BN;

    extern __shared__ uint32_t smu[];
    uint32_t* Ah = smu;
    uint32_t* Al = smu + A_TILE_U32;
    uint32_t* Bh = smu + 2 * A_TILE_U32;
    uint32_t* Bl = Bh + B_TILE_U32;

    const float* Ab = A + sA * (size_t)e;
    const float* Bb = B + sB * (size_t)e;
    float*       Cb = C + sC * (size_t)e;

    int tid = threadIdx.x;
    int warp = tid >> 5, lane = tid & 31;
    int wm = warp >> 1, wn = warp & 1;
    int g = lane >> 2, c = lane & 3;

    // A copy role: 16 k-consecutive floats per thread
    int a_row = tid >> 1, a_half = tid & 1;
    int a_src = m0 + a_row < m ? m0 + a_row : m - 1;   // clamp (rows >= m unused)
    const float* Aptr = Ab + (size_t)a_src * K + a_half * 16;
    // B copy role: two k-rows x 8 n floats per thread
    int b_kp = tid >> 4, b_nc = (tid & 15) * 8;
    const float* Bptr = Bb + (size_t)(2 * b_kp) * N + n0 + b_nc;

    float acc[2][8][4];
    #pragma unroll
    for (int i = 0; i < 2; i++)
        #pragma unroll
        for (int j = 0; j < 8; j++)
            #pragma unroll
            for (int q = 0; q < 4; q++) acc[i][j][q] = 0.f;

    float aR[16], bR[16];
    // prefetch stage 0
    #pragma unroll
    for (int j = 0; j < 4; j++) ((float4*)aR)[j] = *(const float4*)(Aptr + j * 4);
    #pragma unroll
    for (int j = 0; j < 2; j++) {
        ((float4*)bR)[j]     = *(const float4*)(Bptr + j * 4);
        ((float4*)bR)[j + 2] = *(const float4*)(Bptr + N + j * 4);
    }

    int nst = K / BK;
    for (int s = 0; s < nst; s++) {
        // ---- convert current regs -> smem (hi/lo bf16 pairs) ----
        {
            uint32_t hh[8], ll[8];
            #pragma unroll
            for (int p = 0; p < 8; p++) {
                float x0 = aR[2 * p], x1 = aR[2 * p + 1];
                uint32_t h = pack2(x0, x1);
                float f0, f1; unpack2(h, f0, f1);
                hh[p] = h;
                ll[p] = pack2(x0 - f0, x1 - f1);
            }
            int idx = a_row * A_STRIDE + a_half * 8;
            *(uint4*)&Ah[idx]     = *(uint4*)&hh[0];
            *(uint4*)&Ah[idx + 4] = *(uint4*)&hh[4];
            *(uint4*)&Al[idx]     = *(uint4*)&ll[0];
            *(uint4*)&Al[idx + 4] = *(uint4*)&ll[4];
        }
        {
            uint32_t hh[8], ll[8];
            #pragma unroll
            for (int j = 0; j < 8; j++) {
                float x0 = bR[j], x1 = bR[8 + j];     // k even, k odd
                uint32_t h = pack2(x0, x1);
                float f0, f1; unpack2(h, f0, f1);
                hh[j] = h;
                ll[j] = pack2(x0 - f0, x1 - f1);
            }
            int idx = b_kp * B_STRIDE + b_nc;
            *(uint4*)&Bh[idx]     = *(uint4*)&hh[0];
            *(uint4*)&Bh[idx + 4] = *(uint4*)&hh[4];
            *(uint4*)&Bl[idx]     = *(uint4*)&ll[0];
            *(uint4*)&Bl[idx + 4] = *(uint4*)&ll[4];
        }
        __syncthreads();

        // ---- prefetch next stage (overlaps with MMA below) ----
        if (s + 1 < nst) {
            int kb = (s + 1) * BK;
            #pragma unroll
            for (int j = 0; j < 4; j++) ((float4*)aR)[j] = *(const float4*)(Aptr + kb + j * 4);
            const float* bp2 = Bptr + (size_t)kb * N;
            #pragma unroll
            for (int j = 0; j < 2; j++) {
                ((float4*)bR)[j]     = *(const float4*)(bp2 + j * 4);
                ((float4*)bR)[j + 2] = *(const float4*)(bp2 + N + j * 4);
            }
        }

        // ---- MMA: 2 k16 substeps ----
        #pragma unroll
        for (int ks = 0; ks < 2; ks++) {
            uint32_t bh[8][2], bl[8][2];
            #pragma unroll
            for (int nt = 0; nt < 8; nt++) {
                int n = wn * 64 + nt * 8 + g;
                int k0 = (ks * 8 + c) * B_STRIDE + n;
                int k1 = (ks * 8 + c + 4) * B_STRIDE + n;
                bh[nt][0] = Bh[k0]; bh[nt][1] = Bh[k1];
                bl[nt][0] = Bl[k0]; bl[nt][1] = Bl[k1];
            }
            #pragma unroll
            for (int mt = 0; mt < 2; mt++) {
                int row = wm * 32 + mt * 16 + g;
                int i0 = row * A_STRIDE + ks * 8 + c;
                int i1 = (row + 8) * A_STRIDE + ks * 8 + c;
                uint32_t ah[4], al[4];
                ah[0] = Ah[i0]; ah[1] = Ah[i1]; ah[2] = Ah[i0 + 4]; ah[3] = Ah[i1 + 4];
                al[0] = Al[i0]; al[1] = Al[i1]; al[2] = Al[i0 + 4]; al[3] = Al[i1 + 4];
                #pragma unroll
                for (int nt = 0; nt < 8; nt++) {
                    mma_bf16(acc[mt][nt], ah, bh[nt]);
                    mma_bf16(acc[mt][nt], ah, bl[nt]);
                    mma_bf16(acc[mt][nt], al, bh[nt]);
                }
            }
        }
        __syncthreads();
    }

    // ---- epilogue ----
    #pragma unroll
    for (int mt = 0; mt < 2; mt++) {
        int r = m0 + wm * 32 + mt * 16 + g;
        #pragma unroll
        for (int nt = 0; nt < 8; nt++) {
            int col = n0 + wn * 64 + nt * 8 + c * 2;
            if (r < m)
                *(float2*)&Cb[(size_t)r * N + col] = make_float2(acc[mt][nt][0], acc[mt][nt][1]);
            if (r + 8 < m)
                *(float2*)&Cb[(size_t)(r + 8) * N + col] = make_float2(acc[mt][nt][2], acc[mt][nt][3]);
        }
    }
}

// ---------------- small kernels ------------------------------------------------
__global__ void zero_cnt_kernel() {
    if (threadIdx.x < NE) g_cnt[threadIdx.x] = 0;
}

__global__ void pack_qkv_kernel(const float* __restrict__ Wq, const float* __restrict__ Wk,
                                const float* __restrict__ Wv) {
    int idx = blockIdx.x * blockDim.x + threadIdx.x;
    if (idx >= DIM * QKVN) return;
    int k = idx / QKVN, n = idx % QKVN;
    float v;
    if (n < 2048)      v = Wq[k * 2048 + n];
    else if (n < 2560) v = Wk[k * 512 + (n - 2048)];
    else               v = Wv[k * 512 + (n - 2560)];
    g_wqkv[idx] = v;
}

__global__ void rmsnorm_kernel(const float* __restrict__ x,
                               const float* __restrict__ w,
                               float* __restrict__ o) {
    int row = blockIdx.x;
    const float* xr = x + (size_t)row * DIM;
    float s = 0.f;
    for (int i = threadIdx.x; i < DIM; i += blockDim.x) {
        float v = xr[i];
        s += v * v;
    }
    __shared__ float red[32];
    int lane = threadIdx.x & 31, wid = threadIdx.x >> 5;
    #pragma unroll
    for (int off = 16; off; off >>= 1) s += __shfl_down_sync(0xffffffffu, s, off);
    if (lane == 0) red[wid] = s;
    __syncthreads();
    if (wid == 0) {
        float t = (lane < (blockDim.x >> 5)) ? red[lane] : 0.f;
        #pragma unroll
        for (int off = 16; off; off >>= 1) t += __shfl_down_sync(0xffffffffu, t, off);
        if (lane == 0) red[0] = t;
    }
    __syncthreads();
    float scale = rsqrtf(red[0] / (float)DIM + 1e-5f);
    float* orow = o + (size_t)row * DIM;
    for (int i = threadIdx.x; i < DIM; i += blockDim.x)
        orow[i] = xr[i] * scale * w[i];
}

__global__ void add_kernel(const float* __restrict__ a, const float* __restrict__ b,
                           float* __restrict__ o, int n) {
    int i = blockIdx.x * blockDim.x + threadIdx.x;
    if (i < n) o[i] = a[i] + b[i];
}

__global__ void rope_kernel(float* __restrict__ x, const int* __restrict__ pos,
                            int heads, int stride, int off) {
    int idx = blockIdx.x * blockDim.x + threadIdx.x;
    int total = SEQ * heads * (HD / 2);
    if (idx >= total) return;
    int d = idx & 31;
    int t = idx >> 5;
    int h = t % heads;
    int s = t / heads;
    double invd = pow(1.0e6, -(double)d / 32.0);
    float ang = (float)((double)pos[s] * invd);
    float cs, sn;
    sincosf(ang, &sn, &cs);
    float* p = x + (size_t)s * stride + off + h * HD;
    float x1 = p[d], x2 = p[d + 32];
    p[d]      = x1 * cs - x2 * sn;
    p[d + 32] = x2 * cs + x1 * sn;
}

__global__ void __launch_bounds__(64)
attn_kernel(const float* __restrict__ qkv, float* __restrict__ o) {
    __shared__ float Ks[64][64];
    __shared__ float Vs[64][64];
    __shared__ float Ss[64][65];
    int qt = blockIdx.x, h = blockIdx.y;
    int tid = threadIdx.x;
    int row = qt * 64 + tid;
    int kvh = h >> 2;

    float qr[64], acc[64];
    const float* qp = qkv + (size_t)row * QKVN + h * HD;
    #pragma unroll
    for (int i = 0; i < 16; i++) ((float4*)qr)[i] = ((const float4*)qp)[i];
    #pragma unroll
    for (int i = 0; i < 64; i++) acc[i] = 0.f;
    float m = -1e30f, l = 0.f;

    for (int kt = 0; kt <= qt; kt++) {
        const float* kp = qkv + (size_t)(kt * 64 + tid) * QKVN + 2048 + kvh * HD;
        const float* vp = qkv + (size_t)(kt * 64 + tid) * QKVN + 2560 + kvh * HD;
        #pragma unroll
        for (int i = 0; i < 16; i++) {
            ((float4*)Ks[tid])[i] = ((const float4*)kp)[i];
            ((float4*)Vs[tid])[i] = ((const float4*)vp)[i];
        }
        __syncthreads();

        int jmax = (kt == qt) ? (tid + 1) : 64;
        float mloc = -1e30f;
        for (int j = 0; j < jmax; j++) {
            float s = 0.f;
            #pragma unroll
            for (int d = 0; d < 64; d += 4) {
                float4 k4 = *(const float4*)&Ks[j][d];
                s += qr[d] * k4.x + qr[d + 1] * k4.y + qr[d + 2] * k4.z + qr[d + 3] * k4.w;
            }
            s *= 0.125f;
            Ss[tid][j] = s;
            mloc = fmaxf(mloc, s);
        }
        float mnew = fmaxf(m, mloc);
        float sc = expf(m - mnew);
        l *= sc;
        #pragma unroll
        for (int d = 0; d < 64; d++) acc[d] *= sc;
        for (int j = 0; j < jmax; j++) {
            float p = expf(Ss[tid][j] - mnew);
            l += p;
            #pragma unroll
            for (int d = 0; d < 64; d += 4) {
                float4 v4 = *(const float4*)&Vs[j][d];
                acc[d]     += p * v4.x;
                acc[d + 1] += p * v4.y;
                acc[d + 2] += p * v4.z;
                acc[d + 3] += p * v4.w;
            }
        }
        m = mnew;
        __syncthreads();
    }
    float inv = 1.f / l;
    float* op = o + (size_t)row * (NH * HD) + h * HD;
    #pragma unroll
    for (int d = 0; d < 64; d++) op[d] = acc[d] * inv;
}

__global__ void router_kernel(const float* __restrict__ x, const float* __restrict__ Wr) {
    int warp = (blockIdx.x * blockDim.x + threadIdx.x) >> 5;
    int lane = threadIdx.x & 31;
    if (warp >= SEQ) return;
    const float* xr = x + (size_t)warp * DIM;
    float acc[NE];
    #pragma unroll
    for (int e = 0; e < NE; e++) acc[e] = 0.f;
    for (int d = lane; d < DIM; d += 32) {
        float xv = xr[d];
        #pragma unroll
        for (int e = 0; e < NE; e++) acc[e] += xv * Wr[d * NE + e];
    }
    #pragma unroll
    for (int e = 0; e < NE; e++)
        #pragma unroll
        for (int off = 16; off; off >>= 1)
            acc[e] += __shfl_down_sync(0xffffffffu, acc[e], off);
    if (lane == 0) {
        int i1 = 0;
        #pragma unroll
        for (int e = 1; e < NE; e++) if (acc[e] > acc[i1]) i1 = e;
        int i2 = (i1 == 0) ? 1 : 0;
        #pragma unroll
        for (int e = 0; e < NE; e++) if (e != i1 && acc[e] > acc[i2]) i2 = e;
        float w1 = 1.f / (1.f + expf(acc[i2] - acc[i1]));
        int s0 = atomicAdd(&g_cnt[i1], 1);
        int s1 = atomicAdd(&g_cnt[i2], 1);
        g_eid[warp * 2]  = i1; g_eid[warp * 2 + 1]  = i2;
        g_slot[warp * 2] = s0; g_slot[warp * 2 + 1] = s1;
        g_w[warp * 2]    = w1; g_w[warp * 2 + 1]    = 1.f - w1;
    }
}

__global__ void gather_kernel(const float* __restrict__ x) {
    int pair = blockIdx.x;
    int n = pair >> 1, j = pair & 1;
    int e = g_eid[n * 2 + j], s = g_slot[n * 2 + j];
    const float4* src = (const float4*)(x + (size_t)n * DIM);
    float4* dst = (float4*)(g_xe + ((size_t)e * CAP + s) * DIM);
    for (int i = threadIdx.x; i < DIM / 4; i += blockDim.x) dst[i] = src[i];
}

__global__ void silu_mul_kernel() {
    int e = blockIdx.z;
    int r = blockIdx.y;
    if (r >= g_cnt[e]) return;
    size_t base = ((size_t)e * CAP + r) * FF;
    int c = blockIdx.x * blockDim.x + threadIdx.x;
    float g = g_gate[base + c];
    float u = g_up[base + c];
    g_gate[base + c] = (g / (1.f + expf(-g))) * u;
}

__global__ void combine_kernel(float* __restrict__ out) {
    int idx = blockIdx.x * blockDim.x + threadIdx.x;
    if (idx >= SEQ * DIM) return;
    int n = idx >> 11;
    int d = idx & (DIM - 1);
    int e0 = g_eid[n * 2],  e1 = g_eid[n * 2 + 1];
    int s0 = g_slot[n * 2], s1 = g_slot[n * 2 + 1];
    out[idx] = g_h2[idx]
             + g_w[n * 2]     * g_down[((size_t)e0 * CAP + s0) * DIM + d]
             + g_w[n * 2 + 1] * g_down[((size_t)e1 * CAP + s1) * DIM + d];
}

// ---------------- launch -------------------------------------------------------
extern "C" void kernel_launch(void* const* d_in, const int* in_sizes, int n_in,
                              void* d_out, int out_size) {
    const float* hidden = (const float*)d_in[0];
    const int*   pos    = (const int*)  d_in[1];
    const float* ln1    = (const float*)d_in[2];
    const float* Wq     = (const float*)d_in[3];
    const float* Wk     = (const float*)d_in[4];
    const float* Wv     = (const float*)d_in[5];
    const float* Wo     = (const float*)d_in[6];
    const float* ln2    = (const float*)d_in[7];
    const float* Wr     = (const float*)d_in[8];
    const float* W1     = (const float*)d_in[9];
    const float* W3     = (const float*)d_in[10];
    const float* W2     = (const float*)d_in[11];
    float* out = (float*)d_out;

    float *p_hn, *p_wqkv, *p_qkv, *p_attn, *p_h2, *p_hn2, *p_xe, *p_gate, *p_up, *p_down;
    cudaGetSymbolAddress((void**)&p_hn,   g_hn);
    cudaGetSymbolAddress((void**)&p_wqkv, g_wqkv);
    cudaGetSymbolAddress((void**)&p_qkv,  g_qkv);
    cudaGetSymbolAddress((void**)&p_attn, g_attn);
    cudaGetSymbolAddress((void**)&p_h2,   g_h2);
    cudaGetSymbolAddress((void**)&p_hn2,  g_hn2);
    cudaGetSymbolAddress((void**)&p_xe,   g_xe);
    cudaGetSymbolAddress((void**)&p_gate, g_gate);
    cudaGetSymbolAddress((void**)&p_up,   g_up);
    cudaGetSymbolAddress((void**)&p_down, g_down);
    int* p_cnt;
    cudaGetSymbolAddress((void**)&p_cnt, g_cnt);

    zero_cnt_kernel<<<1, 32>>>();
    rmsnorm_kernel<<<SEQ, 256>>>(hidden, ln1, p_hn);
    pack_qkv_kernel<<<(DIM * QKVN + 255) / 256, 256>>>(Wq, Wk, Wv);

    // QKV projection: [2048,2048] @ [2048,3072]
    gemm_tc<<<dim3(QKVN / BN, SEQ / BM, 1), 256, GSMEM_BYTES>>>(
        p_hn, p_wqkv, p_qkv, SEQ, QKVN, DIM, 0, 0, 0, 0);

    rope_kernel<<<(SEQ * NH * (HD / 2) + 255) / 256, 256>>>(p_qkv, pos, NH, QKVN, 0);
    rope_kernel<<<(SEQ * KVH * (HD / 2) + 255) / 256, 256>>>(p_qkv, pos, KVH, QKVN, 2048);

    attn_kernel<<<dim3(SEQ / 64, NH, 1), 64>>>(p_qkv, p_attn);

    // O projection + residual
    gemm_tc<<<dim3(DIM / BN, SEQ / BM, 1), 256, GSMEM_BYTES>>>(
        p_attn, Wo, p_hn, SEQ, DIM, NH * HD, 0, 0, 0, 0);
    add_kernel<<<(SEQ * DIM + 255) / 256, 256>>>(hidden, p_hn, p_h2, SEQ * DIM);

    rmsnorm_kernel<<<SEQ, 256>>>(p_h2, ln2, p_hn2);
    router_kernel<<<(SEQ * 32 + 255) / 256, 256>>>(p_hn2, Wr);
    gather_kernel<<<SEQ * 2, 256>>>(p_hn2);

    // expert GEMMs (device-count early exit)
    gemm_tc<<<dim3(FF / BN, CAP / BM, NE), 256, GSMEM_BYTES>>>(
        p_xe, W1, p_gate, CAP, FF, DIM, p_cnt,
        (size_t)CAP * DIM, (size_t)DIM * FF, (size_t)CAP * FF);
    gemm_tc<<<dim3(FF / BN, CAP / BM, NE), 256, GSMEM_BYTES>>>(
        p_xe, W3, p_up, CAP, FF, DIM, p_cnt,
        (size_t)CAP * DIM, (size_t)DIM * FF, (size_t)CAP * FF);
    silu_mul_kernel<<<dim3(FF / 256, CAP, NE), 256>>>();
    gemm_tc<<<dim3(DIM / BN, CAP / BM, NE), 256, GSMEM_BYTES>>>(
        p_gate, W2, p_down, CAP, DIM, FF, p_cnt,
        (size_t)CAP * FF, (size_t)FF * DIM, (size_t)CAP * DIM);

    combine_kernel<<<(SEQ * DIM + 255) / 256, 256>>>(out);
}

// round 6
// speedup vs baseline: 1.9830x; 1.0605x over previous
#include <cuda_runtime.h>
#include <cuda_bf16.h>
#include <math.h>
#include <stdint.h>

#define DIM   2048
#define SEQ   2048
#define NH    32
#define KVH   8
#define HD    64
#define NE    8
#define FF    7168
#define CAP   2048
#define QKVN  3072

// ---------------- scratch (device globals) ------------------------------------
static __device__ float g_hn  [SEQ * DIM];
static __device__ float g_wqkv[DIM * QKVN];
static __device__ float g_qkv [SEQ * QKVN];
static __device__ float g_attn[SEQ * NH * HD];
static __device__ float g_h2  [SEQ * DIM];
static __device__ float g_hn2 [SEQ * DIM];
static __device__ float g_xe  [(size_t)NE * CAP * DIM];
static __device__ float g_gate[(size_t)NE * CAP * FF];
static __device__ float g_up  [(size_t)NE * CAP * FF];
static __device__ float g_down[(size_t)NE * CAP * DIM];
static __device__ int   g_cnt [NE];
static __device__ int   g_eid [SEQ * 2];
static __device__ int   g_slot[SEQ * 2];
static __device__ float g_w   [SEQ * 2];

// ---------------- helpers ------------------------------------------------------
__device__ __forceinline__ uint32_t pack2(float x0, float x1) {
    uint32_t u;
    asm("cvt.rn.bf16x2.f32 %0, %1, %2;" : "=r"(u) : "f"(x1), "f"(x0));
    return u;
}
__device__ __forceinline__ void unpack2(uint32_t u, float& f0, float& f1) {
    __nv_bfloat162 t = *reinterpret_cast<__nv_bfloat162*>(&u);
    f0 = __bfloat162float(t.x);
    f1 = __bfloat162float(t.y);
}
__device__ __forceinline__ void mma_bf16(float* d, const uint32_t* a, const uint32_t* b) {
    asm volatile(
        "mma.sync.aligned.m16n8k16.row.col.f32.bf16.bf16.f32 "
        "{%0,%1,%2,%3}, {%4,%5,%6,%7}, {%8,%9}, {%0,%1,%2,%3};"
        : "+f"(d[0]), "+f"(d[1]), "+f"(d[2]), "+f"(d[3])
        : "r"(a[0]), "r"(a[1]), "r"(a[2]), "r"(a[3]), "r"(b[0]), "r"(b[1]));
}

// ---------------- 3xBF16 split-precision GEMM (128x128x32, double-buffered) ----
#define BM 128
#define BN 128
#define BK 32
#define A_STRIDE 20
#define B_STRIDE 136
#define A_TILE_U32 (BM * A_STRIDE)   // 2560
#define B_TILE_U32 (16 * B_STRIDE)   // 2176
#define STAGE_U32 (2 * A_TILE_U32 + 2 * B_TILE_U32)   // 9472
#define GSMEM_BYTES (2 * STAGE_U32 * 4)               // 75776

__global__ void __launch_bounds__(256)
gemm_tc(const float* __restrict__ A, const float* __restrict__ B, float* __restrict__ C,
        int M, int N, int K, const int* __restrict__ cnt,
        size_t sA, size_t sB, size_t sC) {
    int e = blockIdx.z;
    int m = cnt ? cnt[e] : M;
    int m0 = blockIdx.y * BM;
    if (m0 >= m) return;
    int n0 = blockIdx.x * BN;

    extern __shared__ uint32_t smu[];
    uint32_t* bufs[2] = { smu, smu + STAGE_U32 };

    const float* Ab = A + sA * (size_t)e;
    const float* Bb = B + sB * (size_t)e;
    float*       Cb = C + sC * (size_t)e;

    int tid = threadIdx.x;
    int warp = tid >> 5, lane = tid & 31;
    int wm = warp >> 1, wn = warp & 1;
    int g = lane >> 2, c = lane & 3;

    int a_row = tid >> 1, a_half = tid & 1;
    int a_src = m0 + a_row < m ? m0 + a_row : m - 1;
    const float* Aptr = Ab + (size_t)a_src * K + a_half * 16;
    int b_kp = tid >> 4, b_nc = (tid & 15) * 8;
    const float* Bptr = Bb + (size_t)(2 * b_kp) * N + n0 + b_nc;

    float acc[2][8][4];
    #pragma unroll
    for (int i = 0; i < 2; i++)
        #pragma unroll
        for (int j = 0; j < 8; j++)
            #pragma unroll
            for (int q = 0; q < 4; q++) acc[i][j][q] = 0.f;

    float aR[16], bR[16];

    auto load_regs = [&](int kb) {
        #pragma unroll
        for (int j = 0; j < 4; j++) ((float4*)aR)[j] = *(const float4*)(Aptr + kb + j * 4);
        const float* bp2 = Bptr + (size_t)kb * N;
        #pragma unroll
        for (int j = 0; j < 2; j++) {
            ((float4*)bR)[j]     = *(const float4*)(bp2 + j * 4);
            ((float4*)bR)[j + 2] = *(const float4*)(bp2 + N + j * 4);
        }
    };
    auto convert_store = [&](uint32_t* buf) {
        uint32_t* Ah = buf;
        uint32_t* Al = buf + A_TILE_U32;
        uint32_t* Bh = buf + 2 * A_TILE_U32;
        uint32_t* Bl = Bh + B_TILE_U32;
        {
            uint32_t hh[8], ll[8];
            #pragma unroll
            for (int p = 0; p < 8; p++) {
                float x0 = aR[2 * p], x1 = aR[2 * p + 1];
                uint32_t hv = pack2(x0, x1);
                float f0, f1; unpack2(hv, f0, f1);
                hh[p] = hv;
                ll[p] = pack2(x0 - f0, x1 - f1);
            }
            int idx = a_row * A_STRIDE + a_half * 8;
            *(uint4*)&Ah[idx]     = *(uint4*)&hh[0];
            *(uint4*)&Ah[idx + 4] = *(uint4*)&hh[4];
            *(uint4*)&Al[idx]     = *(uint4*)&ll[0];
            *(uint4*)&Al[idx + 4] = *(uint4*)&ll[4];
        }
        {
            uint32_t hh[8], ll[8];
            #pragma unroll
            for (int j = 0; j < 8; j++) {
                float x0 = bR[j], x1 = bR[8 + j];
                uint32_t hv = pack2(x0, x1);
                float f0, f1; unpack2(hv, f0, f1);
                hh[j] = hv;
                ll[j] = pack2(x0 - f0, x1 - f1);
            }
            int idx = b_kp * B_STRIDE + b_nc;
            *(uint4*)&Bh[idx]     = *(uint4*)&hh[0];
            *(uint4*)&Bh[idx + 4] = *(uint4*)&hh[4];
            *(uint4*)&Bl[idx]     = *(uint4*)&ll[0];
            *(uint4*)&Bl[idx + 4] = *(uint4*)&ll[4];
        }
    };

    int nst = K / BK;
    load_regs(0);
    convert_store(bufs[0]);

    for (int s = 0; s < nst; s++) {
        uint32_t* buf = bufs[s & 1];
        uint32_t* Ah = buf;
        uint32_t* Al = buf + A_TILE_U32;
        uint32_t* Bh = buf + 2 * A_TILE_U32;
        uint32_t* Bl = Bh + B_TILE_U32;
        __syncthreads();
        if (s + 1 < nst) load_regs((s + 1) * BK);

        #pragma unroll
        for (int ks = 0; ks < 2; ks++) {
            uint32_t bh[8][2], bl[8][2];
            #pragma unroll
            for (int nt = 0; nt < 8; nt++) {
                int n = wn * 64 + nt * 8 + g;
                int k0 = (ks * 8 + c) * B_STRIDE + n;
                int k1 = (ks * 8 + c + 4) * B_STRIDE + n;
                bh[nt][0] = Bh[k0]; bh[nt][1] = Bh[k1];
                bl[nt][0] = Bl[k0]; bl[nt][1] = Bl[k1];
            }
            #pragma unroll
            for (int mt = 0; mt < 2; mt++) {
                int row = wm * 32 + mt * 16 + g;
                int i0 = row * A_STRIDE + ks * 8 + c;
                int i1 = (row + 8) * A_STRIDE + ks * 8 + c;
                uint32_t ah[4], al[4];
                ah[0] = Ah[i0]; ah[1] = Ah[i1]; ah[2] = Ah[i0 + 4]; ah[3] = Ah[i1 + 4];
                al[0] = Al[i0]; al[1] = Al[i1]; al[2] = Al[i0 + 4]; al[3] = Al[i1 + 4];
                #pragma unroll
                for (int nt = 0; nt < 8; nt++) {
                    mma_bf16(acc[mt][nt], ah, bh[nt]);
                    mma_bf16(acc[mt][nt], ah, bl[nt]);
                    mma_bf16(acc[mt][nt], al, bh[nt]);
                }
            }
        }
        if (s + 1 < nst) convert_store(bufs[(s + 1) & 1]);
    }

    #pragma unroll
    for (int mt = 0; mt < 2; mt++) {
        int r = m0 + wm * 32 + mt * 16 + g;
        #pragma unroll
        for (int nt = 0; nt < 8; nt++) {
            int col = n0 + wn * 64 + nt * 8 + c * 2;
            if (r < m)
                *(float2*)&Cb[(size_t)r * N + col] = make_float2(acc[mt][nt][0], acc[mt][nt][1]);
            if (r + 8 < m)
                *(float2*)&Cb[(size_t)(r + 8) * N + col] = make_float2(acc[mt][nt][2], acc[mt][nt][3]);
        }
    }
}

// ---------------- tensor-core flash attention (3xbf16 both GEMMs) --------------
#define KV_STR 36

__global__ void __launch_bounds__(128)
attn_tc(const float* __restrict__ qkv, float* __restrict__ o) {
    __shared__ uint32_t Kh[64 * KV_STR], Kl[64 * KV_STR];
    __shared__ uint32_t Vh[64 * KV_STR], Vl[64 * KV_STR];
    int qt = blockIdx.x, h = blockIdx.y;
    int tid = threadIdx.x, warp = tid >> 5, lane = tid & 31;
    int g = lane >> 2, c = lane & 3;
    int kvh = h >> 2;

    // Q fragments (scaled by 1/8), split hi/lo; warp handles rows warp*16..+15
    uint32_t Qh[4][4], Ql[4][4];
    {
        int r0 = qt * 64 + warp * 16 + g;
        const float* q0 = qkv + (size_t)r0 * QKVN + h * HD;
        const float* q1 = q0 + 8 * QKVN;
        #pragma unroll
        for (int ks = 0; ks < 4; ks++) {
            #pragma unroll
            for (int half = 0; half < 2; half++) {
                int d = ks * 16 + half * 8 + 2 * c;
                float x0 = q0[d] * 0.125f, x1 = q0[d + 1] * 0.125f;
                float y0 = q1[d] * 0.125f, y1 = q1[d + 1] * 0.125f;
                uint32_t hx = pack2(x0, x1), hy = pack2(y0, y1);
                float fx0, fx1, fy0, fy1;
                unpack2(hx, fx0, fx1);
                unpack2(hy, fy0, fy1);
                Qh[ks][half * 2]     = hx;
                Qh[ks][half * 2 + 1] = hy;
                Ql[ks][half * 2]     = pack2(x0 - fx0, x1 - fx1);
                Ql[ks][half * 2 + 1] = pack2(y0 - fy0, y1 - fy1);
            }
        }
    }

    float acc[8][4];
    #pragma unroll
    for (int nt = 0; nt < 8; nt++)
        #pragma unroll
        for (int q = 0; q < 4; q++) acc[nt][q] = 0.f;
    float m0 = -1e30f, m1 = -1e30f, l0 = 0.f, l1 = 0.f;

    for (int kt = 0; kt <= qt; kt++) {
        // ---- stage K (pairs along d) ----
        {
            int tok = tid >> 1, half = tid & 1;
            const float* kp = qkv + (size_t)(kt * 64 + tok) * QKVN + 2048 + kvh * HD + half * 32;
            float v[32];
            #pragma unroll
            for (int j = 0; j < 8; j++) ((float4*)v)[j] = ((const float4*)kp)[j];
            int base = tok * KV_STR + half * 16;
            #pragma unroll
            for (int j = 0; j < 16; j++) {
                uint32_t hv = pack2(v[2 * j], v[2 * j + 1]);
                float f0, f1; unpack2(hv, f0, f1);
                Kh[base + j] = hv;
                Kl[base + j] = pack2(v[2 * j] - f0, v[2 * j + 1] - f1);
            }
        }
        // ---- stage V transposed (pairs along kv): Vsm[d][kvpair] ----
        {
            const float* vp0 = qkv + (size_t)(kt * 64 + 2 * lane) * QKVN + 2560 + kvh * HD + warp * 16;
            const float* vp1 = vp0 + QKVN;
            float va[16], vb[16];
            #pragma unroll
            for (int j = 0; j < 4; j++) {
                ((float4*)va)[j] = ((const float4*)vp0)[j];
                ((float4*)vb)[j] = ((const float4*)vp1)[j];
            }
            #pragma unroll
            for (int i = 0; i < 16; i++) {
                uint32_t hv = pack2(va[i], vb[i]);
                float f0, f1; unpack2(hv, f0, f1);
                int idx = (warp * 16 + i) * KV_STR + lane;
                Vh[idx] = hv;
                Vl[idx] = pack2(va[i] - f0, vb[i] - f1);
            }
        }
        __syncthreads();

        // ---- S = Q K^T (3xbf16) ----
        float s[8][4];
        #pragma unroll
        for (int nt = 0; nt < 8; nt++)
            #pragma unroll
            for (int q = 0; q < 4; q++) s[nt][q] = 0.f;
        #pragma unroll
        for (int ks = 0; ks < 4; ks++) {
            #pragma unroll
            for (int nt = 0; nt < 8; nt++) {
                int idx = (nt * 8 + g) * KV_STR + ks * 8 + c;
                uint32_t bh[2] = { Kh[idx], Kh[idx + 4] };
                uint32_t bl[2] = { Kl[idx], Kl[idx + 4] };
                mma_bf16(s[nt], Qh[ks], bh);
                mma_bf16(s[nt], Ql[ks], bh);
                mma_bf16(s[nt], Qh[ks], bl);
            }
        }
        // causal mask (diagonal tile)
        if (kt == qt) {
            int row0 = warp * 16 + g, row1 = row0 + 8;
            #pragma unroll
            for (int nt = 0; nt < 8; nt++) {
                int col = nt * 8 + 2 * c;
                if (col > row0)     s[nt][0] = -1e30f;
                if (col + 1 > row0) s[nt][1] = -1e30f;
                if (col > row1)     s[nt][2] = -1e30f;
                if (col + 1 > row1) s[nt][3] = -1e30f;
            }
        }
        // ---- online softmax ----
        float mx0 = -1e30f, mx1 = -1e30f;
        #pragma unroll
        for (int nt = 0; nt < 8; nt++) {
            mx0 = fmaxf(mx0, fmaxf(s[nt][0], s[nt][1]));
            mx1 = fmaxf(mx1, fmaxf(s[nt][2], s[nt][3]));
        }
        mx0 = fmaxf(mx0, __shfl_xor_sync(0xffffffffu, mx0, 1));
        mx0 = fmaxf(mx0, __shfl_xor_sync(0xffffffffu, mx0, 2));
        mx1 = fmaxf(mx1, __shfl_xor_sync(0xffffffffu, mx1, 1));
        mx1 = fmaxf(mx1, __shfl_xor_sync(0xffffffffu, mx1, 2));
        float mn0 = fmaxf(m0, mx0), mn1 = fmaxf(m1, mx1);
        float sc0 = expf(m0 - mn0), sc1 = expf(m1 - mn1);
        m0 = mn0; m1 = mn1;
        l0 *= sc0; l1 *= sc1;
        #pragma unroll
        for (int nt = 0; nt < 8; nt++) {
            acc[nt][0] *= sc0; acc[nt][1] *= sc0;
            acc[nt][2] *= sc1; acc[nt][3] *= sc1;
        }
        // P = exp(S - m) in place; accumulate partial l (local cols)
        #pragma unroll
        for (int nt = 0; nt < 8; nt++) {
            s[nt][0] = expf(s[nt][0] - m0);
            s[nt][1] = expf(s[nt][1] - m0);
            s[nt][2] = expf(s[nt][2] - m1);
            s[nt][3] = expf(s[nt][3] - m1);
            l0 += s[nt][0] + s[nt][1];
            l1 += s[nt][2] + s[nt][3];
        }
        // repack P c-layout -> a-layout fragments, split hi/lo
        uint32_t Ph[4][4], Pl[4][4];
        #pragma unroll
        for (int j = 0; j < 4; j++) {
            #pragma unroll
            for (int q = 0; q < 4; q++) {
                int nt = 2 * j + (q >> 1);
                float x0 = s[nt][(q & 1) * 2], x1 = s[nt][(q & 1) * 2 + 1];
                uint32_t hv = pack2(x0, x1);
                float f0, f1; unpack2(hv, f0, f1);
                Ph[j][q] = hv;
                Pl[j][q] = pack2(x0 - f0, x1 - f1);
            }
        }
        // ---- O += P V (3xbf16) ----
        #pragma unroll
        for (int j = 0; j < 4; j++) {
            #pragma unroll
            for (int nt = 0; nt < 8; nt++) {
                int idx = (nt * 8 + g) * KV_STR + j * 8 + c;
                uint32_t bh[2] = { Vh[idx], Vh[idx + 4] };
                uint32_t bl[2] = { Vl[idx], Vl[idx + 4] };
                mma_bf16(acc[nt], Ph[j], bh);
                mma_bf16(acc[nt], Pl[j], bh);
                mma_bf16(acc[nt], Ph[j], bl);
            }
        }
        __syncthreads();
    }

    // final l reduction across c-quad + store
    l0 += __shfl_xor_sync(0xffffffffu, l0, 1);
    l0 += __shfl_xor_sync(0xffffffffu, l0, 2);
    l1 += __shfl_xor_sync(0xffffffffu, l1, 1);
    l1 += __shfl_xor_sync(0xffffffffu, l1, 2);
    float inv0 = 1.f / l0, inv1 = 1.f / l1;
    int r0 = qt * 64 + warp * 16 + g;
    float* op0 = o + (size_t)r0 * (NH * HD) + h * HD;
    float* op1 = op0 + 8 * (NH * HD);
    #pragma unroll
    for (int nt = 0; nt < 8; nt++) {
        *(float2*)&op0[nt * 8 + 2 * c] = make_float2(acc[nt][0] * inv0, acc[nt][1] * inv0);
        *(float2*)&op1[nt * 8 + 2 * c] = make_float2(acc[nt][2] * inv1, acc[nt][3] * inv1);
    }
}

// ---------------- small kernels ------------------------------------------------
__global__ void zero_cnt_kernel() {
    if (threadIdx.x < NE) g_cnt[threadIdx.x] = 0;
}

__global__ void pack_qkv_kernel(const float* __restrict__ Wq, const float* __restrict__ Wk,
                                const float* __restrict__ Wv) {
    int idx = blockIdx.x * blockDim.x + threadIdx.x;
    if (idx >= DIM * QKVN) return;
    int k = idx / QKVN, n = idx % QKVN;
    float v;
    if (n < 2048)      v = Wq[k * 2048 + n];
    else if (n < 2560) v = Wk[k * 512 + (n - 2048)];
    else               v = Wv[k * 512 + (n - 2560)];
    g_wqkv[idx] = v;
}

__global__ void rmsnorm_kernel(const float* __restrict__ x,
                               const float* __restrict__ w,
                               float* __restrict__ o) {
    int row = blockIdx.x;
    const float* xr = x + (size_t)row * DIM;
    float s = 0.f;
    for (int i = threadIdx.x; i < DIM; i += blockDim.x) {
        float v = xr[i];
        s += v * v;
    }
    __shared__ float red[32];
    int lane = threadIdx.x & 31, wid = threadIdx.x >> 5;
    #pragma unroll
    for (int off = 16; off; off >>= 1) s += __shfl_down_sync(0xffffffffu, s, off);
    if (lane == 0) red[wid] = s;
    __syncthreads();
    if (wid == 0) {
        float t = (lane < (blockDim.x >> 5)) ? red[lane] : 0.f;
        #pragma unroll
        for (int off = 16; off; off >>= 1) t += __shfl_down_sync(0xffffffffu, t, off);
        if (lane == 0) red[0] = t;
    }
    __syncthreads();
    float scale = rsqrtf(red[0] / (float)DIM + 1e-5f);
    float* orow = o + (size_t)row * DIM;
    for (int i = threadIdx.x; i < DIM; i += blockDim.x)
        orow[i] = xr[i] * scale * w[i];
}

__global__ void add_kernel(const float* __restrict__ a, const float* __restrict__ b,
                           float* __restrict__ o, int n) {
    int i = blockIdx.x * blockDim.x + threadIdx.x;
    if (i < n) o[i] = a[i] + b[i];
}

__global__ void rope_kernel(float* __restrict__ x, const int* __restrict__ pos,
                            int heads, int stride, int off) {
    int idx = blockIdx.x * blockDim.x + threadIdx.x;
    int total = SEQ * heads * (HD / 2);
    if (idx >= total) return;
    int d = idx & 31;
    int t = idx >> 5;
    int h = t % heads;
    int s = t / heads;
    double invd = pow(1.0e6, -(double)d / 32.0);
    float ang = (float)((double)pos[s] * invd);
    float cs, sn;
    sincosf(ang, &sn, &cs);
    float* p = x + (size_t)s * stride + off + h * HD;
    float x1 = p[d], x2 = p[d + 32];
    p[d]      = x1 * cs - x2 * sn;
    p[d + 32] = x2 * cs + x1 * sn;
}

__global__ void router_kernel(const float* __restrict__ x, const float* __restrict__ Wr) {
    int warp = (blockIdx.x * blockDim.x + threadIdx.x) >> 5;
    int lane = threadIdx.x & 31;
    if (warp >= SEQ) return;
    const float* xr = x + (size_t)warp * DIM;
    float acc[NE];
    #pragma unroll
    for (int e = 0; e < NE; e++) acc[e] = 0.f;
    for (int d = lane; d < DIM; d += 32) {
        float xv = xr[d];
        #pragma unroll
        for (int e = 0; e < NE; e++) acc[e] += xv * Wr[d * NE + e];
    }
    #pragma unroll
    for (int e = 0; e < NE; e++)
        #pragma unroll
        for (int off = 16; off; off >>= 1)
            acc[e] += __shfl_down_sync(0xffffffffu, acc[e], off);
    if (lane == 0) {
        int i1 = 0;
        #pragma unroll
        for (int e = 1; e < NE; e++) if (acc[e] > acc[i1]) i1 = e;
        int i2 = (i1 == 0) ? 1 : 0;
        #pragma unroll
        for (int e = 0; e < NE; e++) if (e != i1 && acc[e] > acc[i2]) i2 = e;
        float w1 = 1.f / (1.f + expf(acc[i2] - acc[i1]));
        int s0 = atomicAdd(&g_cnt[i1], 1);
        int s1 = atomicAdd(&g_cnt[i2], 1);
        g_eid[warp * 2]  = i1; g_eid[warp * 2 + 1]  = i2;
        g_slot[warp * 2] = s0; g_slot[warp * 2 + 1] = s1;
        g_w[warp * 2]    = w1; g_w[warp * 2 + 1]    = 1.f - w1;
    }
}

__global__ void gather_kernel(const float* __restrict__ x) {
    int pair = blockIdx.x;
    int n = pair >> 1, j = pair & 1;
    int e = g_eid[n * 2 + j], s = g_slot[n * 2 + j];
    const float4* src = (const float4*)(x + (size_t)n * DIM);
    float4* dst = (float4*)(g_xe + ((size_t)e * CAP + s) * DIM);
    for (int i = threadIdx.x; i < DIM / 4; i += blockDim.x) dst[i] = src[i];
}

__global__ void silu_mul_kernel() {
    int e = blockIdx.z;
    int r = blockIdx.y;
    if (r >= g_cnt[e]) return;
    size_t base = ((size_t)e * CAP + r) * FF;
    int c = blockIdx.x * blockDim.x + threadIdx.x;
    float g = g_gate[base + c];
    float u = g_up[base + c];
    g_gate[base + c] = (g / (1.f + expf(-g))) * u;
}

__global__ void combine_kernel(float* __restrict__ out) {
    int idx = blockIdx.x * blockDim.x + threadIdx.x;
    if (idx >= SEQ * DIM) return;
    int n = idx >> 11;
    int d = idx & (DIM - 1);
    int e0 = g_eid[n * 2],  e1 = g_eid[n * 2 + 1];
    int s0 = g_slot[n * 2], s1 = g_slot[n * 2 + 1];
    out[idx] = g_h2[idx]
             + g_w[n * 2]     * g_down[((size_t)e0 * CAP + s0) * DIM + d]
             + g_w[n * 2 + 1] * g_down[((size_t)e1 * CAP + s1) * DIM + d];
}

// ---------------- launch -------------------------------------------------------
extern "C" void kernel_launch(void* const* d_in, const int* in_sizes, int n_in,
                              void* d_out, int out_size) {
    const float* hidden = (const float*)d_in[0];
    const int*   pos    = (const int*)  d_in[1];
    const float* ln1    = (const float*)d_in[2];
    const float* Wq     = (const float*)d_in[3];
    const float* Wk     = (const float*)d_in[4];
    const float* Wv     = (const float*)d_in[5];
    const float* Wo     = (const float*)d_in[6];
    const float* ln2    = (const float*)d_in[7];
    const float* Wr     = (const float*)d_in[8];
    const float* W1     = (const float*)d_in[9];
    const float* W3     = (const float*)d_in[10];
    const float* W2     = (const float*)d_in[11];
    float* out = (float*)d_out;

    float *p_hn, *p_wqkv, *p_qkv, *p_attn, *p_h2, *p_hn2, *p_xe, *p_gate, *p_up, *p_down;
    cudaGetSymbolAddress((void**)&p_hn,   g_hn);
    cudaGetSymbolAddress((void**)&p_wqkv, g_wqkv);
    cudaGetSymbolAddress((void**)&p_qkv,  g_qkv);
    cudaGetSymbolAddress((void**)&p_attn, g_attn);
    cudaGetSymbolAddress((void**)&p_h2,   g_h2);
    cudaGetSymbolAddress((void**)&p_hn2,  g_hn2);
    cudaGetSymbolAddress((void**)&p_xe,   g_xe);
    cudaGetSymbolAddress((void**)&p_gate, g_gate);
    cudaGetSymbolAddress((void**)&p_up,   g_up);
    cudaGetSymbolAddress((void**)&p_down, g_down);
    int* p_cnt;
    cudaGetSymbolAddress((void**)&p_cnt, g_cnt);

    static int smem_set = 0;
    if (!smem_set) {
        cudaFuncSetAttribute(gemm_tc, cudaFuncAttributeMaxDynamicSharedMemorySize, GSMEM_BYTES);
        smem_set = 1;
    }

    zero_cnt_kernel<<<1, 32>>>();
    rmsnorm_kernel<<<SEQ, 256>>>(hidden, ln1, p_hn);
    pack_qkv_kernel<<<(DIM * QKVN + 255) / 256, 256>>>(Wq, Wk, Wv);

    // QKV projection: [2048,2048] @ [2048,3072]
    gemm_tc<<<dim3(QKVN / BN, SEQ / BM, 1), 256, GSMEM_BYTES>>>(
        p_hn, p_wqkv, p_qkv, SEQ, QKVN, DIM, 0, 0, 0, 0);

    rope_kernel<<<(SEQ * NH * (HD / 2) + 255) / 256, 256>>>(p_qkv, pos, NH, QKVN, 0);
    rope_kernel<<<(SEQ * KVH * (HD / 2) + 255) / 256, 256>>>(p_qkv, pos, KVH, QKVN, 2048);

    attn_tc<<<dim3(SEQ / 64, NH, 1), 128>>>(p_qkv, p_attn);

    // O projection + residual
    gemm_tc<<<dim3(DIM / BN, SEQ / BM, 1), 256, GSMEM_BYTES>>>(
        p_attn, Wo, p_hn, SEQ, DIM, NH * HD, 0, 0, 0, 0);
    add_kernel<<<(SEQ * DIM + 255) / 256, 256>>>(hidden, p_hn, p_h2, SEQ * DIM);

    rmsnorm_kernel<<<SEQ, 256>>>(p_h2, ln2, p_hn2);
    router_kernel<<<(SEQ * 32 + 255) / 256, 256>>>(p_hn2, Wr);
    gather_kernel<<<SEQ * 2, 256>>>(p_hn2);

    // expert GEMMs (device-count early exit)
    gemm_tc<<<dim3(FF / BN, CAP / BM, NE), 256, GSMEM_BYTES>>>(
        p_xe, W1, p_gate, CAP, FF, DIM, p_cnt,
        (size_t)CAP * DIM, (size_t)DIM * FF, (size_t)CAP * FF);
    gemm_tc<<<dim3(FF / BN, CAP / BM, NE), 256, GSMEM_BYTES>>>(
        p_xe, W3, p_up, CAP, FF, DIM, p_cnt,
        (size_t)CAP * DIM, (size_t)DIM * FF, (size_t)CAP * FF);
    silu_mul_kernel<<<dim3(FF / 256, CAP, NE), 256>>>();
    gemm_tc<<<dim3(DIM / BN, CAP / BM, NE), 256, GSMEM_BYTES>>>(
        p_gate, W2, p_down, CAP, DIM, FF, p_cnt,
        (size_t)CAP * FF, (size_t)FF * DIM, (size_t)CAP * DIM);

    combine_kernel<<<(SEQ * DIM + 255) / 256, 256>>>(out);
}